// round 2
// baseline (speedup 1.0000x reference)
#include <cuda_runtime.h>
#include <math.h>

#define B_ 8
#define T_ 1024
#define C_ 2048
#define H_ 16
#define D_ 128
#define C3_ (3*C_)

// Scratch (device globals: allocation-free kernel_launch).
__device__ float g_qkv[(size_t)B_*T_*C3_];   // [B*T, 3C]
__device__ float g_y  [(size_t)B_*T_*C_];    // [B*T, C]

// ---------------------------------------------------------------------------
// Generic SGEMM: C[M,N] = A[M,K] @ B[K,N] + bias[N]
// 128x128 block tile, BK=8, 256 threads, 8x8 per-thread tile.
// M,N multiples of 128; K multiple of 8 (true for all our shapes).
// ---------------------------------------------------------------------------
__global__ __launch_bounds__(256, 2) void sgemm_bias(
    const float* __restrict__ A, const float* __restrict__ Bm,
    const float* __restrict__ bias, float* __restrict__ C,
    int M, int N, int K)
{
    __shared__ float As[8][128];   // transposed A tile
    __shared__ float Bs[8][128];

    const int tid  = threadIdx.x;
    const int tx   = tid & 15;
    const int ty   = tid >> 4;
    const int aRow = tid >> 1;
    const int aCol = (tid & 1) * 4;
    const int bRow = tid >> 5;
    const int bCol = (tid & 31) * 4;

    const float* Ag = A  + (blockIdx.y * 128 + aRow) * K + aCol;
    const float* Bg = Bm + bRow * N + blockIdx.x * 128 + bCol;

    float acc[8][8];
#pragma unroll
    for (int i = 0; i < 8; i++)
#pragma unroll
        for (int j = 0; j < 8; j++) acc[i][j] = 0.f;

    for (int k0 = 0; k0 < K; k0 += 8) {
        float4 a4 = *(const float4*)(Ag + k0);
        float4 b4 = *(const float4*)(Bg + k0 * N);
        As[aCol+0][aRow] = a4.x;
        As[aCol+1][aRow] = a4.y;
        As[aCol+2][aRow] = a4.z;
        As[aCol+3][aRow] = a4.w;
        *(float4*)&Bs[bRow][bCol] = b4;
        __syncthreads();
#pragma unroll
        for (int kk = 0; kk < 8; kk++) {
            float4 a0 = *(const float4*)&As[kk][ty*8];
            float4 a1 = *(const float4*)&As[kk][ty*8+4];
            float4 b0 = *(const float4*)&Bs[kk][tx*8];
            float4 b1 = *(const float4*)&Bs[kk][tx*8+4];
            float ar[8] = {a0.x,a0.y,a0.z,a0.w,a1.x,a1.y,a1.z,a1.w};
            float br[8] = {b0.x,b0.y,b0.z,b0.w,b1.x,b1.y,b1.z,b1.w};
#pragma unroll
            for (int i = 0; i < 8; i++)
#pragma unroll
                for (int j = 0; j < 8; j++)
                    acc[i][j] = fmaf(ar[i], br[j], acc[i][j]);
        }
        __syncthreads();
    }

    const int row0 = blockIdx.y * 128 + ty * 8;
    const int col0 = blockIdx.x * 128 + tx * 8;
    float4 bi0 = *(const float4*)&bias[col0];
    float4 bi1 = *(const float4*)&bias[col0 + 4];
#pragma unroll
    for (int i = 0; i < 8; i++) {
        float4 o0 = make_float4(acc[i][0]+bi0.x, acc[i][1]+bi0.y,
                                acc[i][2]+bi0.z, acc[i][3]+bi0.w);
        float4 o1 = make_float4(acc[i][4]+bi1.x, acc[i][5]+bi1.y,
                                acc[i][6]+bi1.z, acc[i][7]+bi1.w);
        *(float4*)&C[(row0+i)*N + col0]     = o0;
        *(float4*)&C[(row0+i)*N + col0 + 4] = o1;
    }
}

// ---------------------------------------------------------------------------
// Flash attention (causal), fp32.
// Grid: (T/64, B*H). Block: 256 threads = 16x16.
// Per block: Q tile 64x128 in smem; per KV tile of 64 rows:
//   - K stored TRANSPOSED [d][r] (pad 65: conflict-free transpose stores,
//     near-conflict-free reads with strided column mapping c = tx + 16*j)
//   - S 4x4 per thread, row softmax via 16-lane shuffles (online m/l)
//   - P -> smem [64][68], V row-major [64][132] reusing K's buffer
//   - O += P @ V, 4x8 per thread (rows ty*4+i, cols tx*8+j)
// ---------------------------------------------------------------------------
#define QPAD 132
#define KPAD 65
#define VPAD 132
#define PPAD 68
#define KV_ELEMS (64*VPAD)   // 8448 >= 128*KPAD (8320)
#define ATTN_SMEM ((64*QPAD + KV_ELEMS + 64*PPAD) * 4)

__global__ __launch_bounds__(256, 2) void attn_kernel()
{
    extern __shared__ __align__(16) float sm[];
    float* Qs  = sm;                      // 64 x 132
    float* KVs = Qs + 64*QPAD;            // K^T 128x65  OR  V 64x132
    float* Ps  = KVs + KV_ELEMS;          // 64 x 68

    const int tid = threadIdx.x;
    const int tx = tid & 15, ty = tid >> 4;
    const int qt = blockIdx.x;
    const int b  = blockIdx.y >> 4, h = blockIdx.y & 15;
    const int q0 = qt * 64;
    const float* base = g_qkv + (size_t)b * T_ * C3_ + h * D_;

    // Load Q tile (64 x 128), float4, coalesced
    for (int i = tid; i < 64*32; i += 256) {
        int r = i >> 5, c = (i & 31) << 2;
        *(float4*)&Qs[r*QPAD + c] =
            *(const float4*)(base + (size_t)(q0 + r) * C3_ + c);
    }

    float m_i[4], l_i[4], O[4][8];
#pragma unroll
    for (int i = 0; i < 4; i++) {
        m_i[i] = -3.0e38f; l_i[i] = 0.f;
#pragma unroll
        for (int j = 0; j < 8; j++) O[i][j] = 0.f;
    }

    const float scale = 0.08838834764831845f;  // 1/sqrt(128)

    for (int t = 0; t <= qt; ++t) {
        const int k0 = t * 64;
        __syncthreads();  // prev iter's P/V reads done; Q visible (t=0)

        // Load K tile transposed: KVs[d*65 + r]. Global read coalesced
        // (32 lanes = 32 consecutive d of one row); smem store conflict-free
        // (bank = (d*65 + r) % 32 = (d + r) % 32, d consecutive per warp).
        for (int i = tid; i < 64*128; i += 256) {
            int r = i >> 7, c = i & 127;
            KVs[c*KPAD + r] = base[C_ + (size_t)(k0 + r)*C3_ + c];
        }
        __syncthreads();

        // S = Q K^T  (thread: rows ty*4+i, cols tx + 16*j)
        float s[4][4];
#pragma unroll
        for (int i = 0; i < 4; i++)
#pragma unroll
            for (int j = 0; j < 4; j++) s[i][j] = 0.f;

#pragma unroll 4
        for (int kk = 0; kk < 128; ++kk) {
            float q[4], k[4];
#pragma unroll
            for (int i = 0; i < 4; i++) q[i] = Qs[(ty*4+i)*QPAD + kk];
#pragma unroll
            for (int j = 0; j < 4; j++) k[j] = KVs[kk*KPAD + tx + 16*j];
#pragma unroll
            for (int i = 0; i < 4; i++)
#pragma unroll
                for (int j = 0; j < 4; j++)
                    s[i][j] = fmaf(q[i], k[j], s[i][j]);
        }

        // Online softmax per row (16 lanes own a row)
#pragma unroll
        for (int i = 0; i < 4; i++) {
            const int gq = q0 + ty*4 + i;
            float sv[4];
            float mt = -3.0e38f;
#pragma unroll
            for (int j = 0; j < 4; j++) {
                int gk = k0 + tx + 16*j;
                float v = s[i][j] * scale;
                if (gk > gq) v = -1.0e9f;   // matches reference mask value
                sv[j] = v;
                mt = fmaxf(mt, v);
            }
#pragma unroll
            for (int o = 8; o >= 1; o >>= 1)
                mt = fmaxf(mt, __shfl_xor_sync(0xffffffffu, mt, o, 16));
            const float mn = fmaxf(m_i[i], mt);
            float sum = 0.f;
#pragma unroll
            for (int j = 0; j < 4; j++) {
                float p = __expf(sv[j] - mn);
                sum += p;
                Ps[(ty*4+i)*PPAD + tx + 16*j] = p;
            }
#pragma unroll
            for (int o = 8; o >= 1; o >>= 1)
                sum += __shfl_xor_sync(0xffffffffu, sum, o, 16);
            const float corr = __expf(m_i[i] - mn);
            l_i[i] = l_i[i] * corr + sum;
            m_i[i] = mn;
#pragma unroll
            for (int j = 0; j < 8; j++) O[i][j] *= corr;
        }
        __syncthreads();  // K reads + P writes done before V overwrites KVs

        // Load V tile row-major (64 x 128), float4
        for (int i = tid; i < 64*32; i += 256) {
            int r = i >> 5, c = (i & 31) << 2;
            *(float4*)&KVs[r*VPAD + c] =
                *(const float4*)(base + 2*C_ + (size_t)(k0 + r)*C3_ + c);
        }
        __syncthreads();

        // O += P @ V   (thread: rows ty*4+i, cols tx*8+j)
        for (int k4 = 0; k4 < 16; ++k4) {
            float p[4][4];
#pragma unroll
            for (int i = 0; i < 4; i++) {
                float4 p4 = *(const float4*)&Ps[(ty*4+i)*PPAD + k4*4];
                p[i][0]=p4.x; p[i][1]=p4.y; p[i][2]=p4.z; p[i][3]=p4.w;
            }
#pragma unroll
            for (int ss = 0; ss < 4; ++ss) {
                int k = k4*4 + ss;
                float4 v0 = *(const float4*)&KVs[k*VPAD + tx*8];
                float4 v1 = *(const float4*)&KVs[k*VPAD + tx*8 + 4];
                float vr[8] = {v0.x,v0.y,v0.z,v0.w,v1.x,v1.y,v1.z,v1.w};
#pragma unroll
                for (int i = 0; i < 4; i++)
#pragma unroll
                    for (int j = 0; j < 8; j++)
                        O[i][j] = fmaf(p[i][ss], vr[j], O[i][j]);
            }
        }
    }

    // Epilogue: y[b*T + row, h*128 + col] = O / l   (head-merge transpose)
#pragma unroll
    for (int i = 0; i < 4; i++) {
        const float inv = 1.0f / l_i[i];
        const size_t row = (size_t)b * T_ + q0 + ty*4 + i;
        float4 o0 = make_float4(O[i][0]*inv, O[i][1]*inv, O[i][2]*inv, O[i][3]*inv);
        float4 o1 = make_float4(O[i][4]*inv, O[i][5]*inv, O[i][6]*inv, O[i][7]*inv);
        *(float4*)&g_y[row*C_ + h*D_ + tx*8]     = o0;
        *(float4*)&g_y[row*C_ + h*D_ + tx*8 + 4] = o1;
    }
}

// ---------------------------------------------------------------------------
extern "C" void kernel_launch(void* const* d_in, const int* in_sizes, int n_in,
                              void* d_out, int out_size)
{
    const float* x      = (const float*)d_in[0];
    const float* W_attn = (const float*)d_in[1];
    const float* b_attn = (const float*)d_in[2];
    const float* W_proj = (const float*)d_in[3];
    const float* b_proj = (const float*)d_in[4];
    float* out = (float*)d_out;

    float* qkv_ptr = nullptr;
    float* y_ptr   = nullptr;
    cudaGetSymbolAddress((void**)&qkv_ptr, g_qkv);
    cudaGetSymbolAddress((void**)&y_ptr,   g_y);

    cudaFuncSetAttribute(attn_kernel,
                         cudaFuncAttributeMaxDynamicSharedMemorySize, ATTN_SMEM);

    // 1) qkv = x @ W_attn + b_attn          [8192, 6144]
    sgemm_bias<<<dim3(C3_/128, (B_*T_)/128), 256>>>(
        x, W_attn, b_attn, qkv_ptr, B_*T_, C3_, C_);

    // 2) causal flash attention -> g_y      [8192, 2048]
    attn_kernel<<<dim3(T_/64, B_*H_), 256, ATTN_SMEM>>>();

    // 3) out = y @ W_proj + b_proj          [8192, 2048]
    sgemm_bias<<<dim3(C_/128, (B_*T_)/128), 256>>>(
        y_ptr, W_proj, b_proj, out, B_*T_, C_, C_);
}

// round 4
// speedup vs baseline: 2.0759x; 2.0759x over previous
#include <cuda_runtime.h>
#include <math.h>
#include <stdint.h>

#define B_ 8
#define T_ 1024
#define C_ 2048
#define H_ 16
#define D_ 128
#define C3_ (3*C_)

// Scratch (device globals: allocation-free kernel_launch).
__device__ float g_qkv[(size_t)B_*T_*C3_];   // [B*T, 3C]
__device__ float g_y  [(size_t)B_*T_*C_];    // [B*T, C]

// ===========================================================================
// helpers (base PTX only — NO sm_103a-suffix instructions; ptxas here targets
// plain sm_103 and rejects tcgen05/TMEM)
// ===========================================================================
__device__ __forceinline__ uint32_t f2tf32(float f) {
    uint32_t r;
    asm("cvt.rna.tf32.f32 %0, %1;" : "=r"(r) : "f"(f));
    return r;
}
__device__ __forceinline__ void mma_tf32(float* d, const uint32_t* a,
                                         uint32_t b0, uint32_t b1) {
    asm volatile(
        "mma.sync.aligned.m16n8k8.row.col.f32.tf32.tf32.f32 "
        "{%0,%1,%2,%3}, {%4,%5,%6,%7}, {%8,%9}, {%0,%1,%2,%3};"
        : "+f"(d[0]), "+f"(d[1]), "+f"(d[2]), "+f"(d[3])
        : "r"(a[0]), "r"(a[1]), "r"(a[2]), "r"(a[3]), "r"(b0), "r"(b1));
}

// ===========================================================================
// tf32 tensor-core GEMM: C[M,N] = A[M,K] @ B[K,N] + bias[N]
// CTA 128x128, BK=32, 256 threads (8 warps, 4x2), warp tile 32x64.
// Smem (dynamic, 64KB): A stages [128][32] swz m*32+(k^((m&7)<<2));
//                       B stages [32][128] swz k*128+(n^((k&3)<<3)).
// All smem accesses (vec stores + fragment loads) are bank-conflict-free.
// M,N mult of 128; K mult of 32.
// ===========================================================================
#define AOFF(s) ((s)*4096)
#define BOFF(s) (8192 + (s)*4096)
#define GEMM_SMEM_B 65536

__global__ __launch_bounds__(256) void gemm_mma(
    const float* __restrict__ A, const float* __restrict__ Bm,
    const float* __restrict__ bias, float* __restrict__ Cc,
    int M, int N, int K)
{
    extern __shared__ __align__(16) uint32_t sm4[];
    const int tid  = threadIdx.x;
    const int lane = tid & 31;
    const int warp = tid >> 5;
    const int wm = warp & 3, wn = warp >> 2;
    const int m0 = blockIdx.y * 128, n0 = blockIdx.x * 128;

    const float* Ag = A + (size_t)m0 * K;
    const float* Bg = Bm + n0;
    const int NIT = K >> 5;

    float acc[2][8][4];
#pragma unroll
    for (int i = 0; i < 2; ++i)
#pragma unroll
        for (int j = 0; j < 8; ++j)
#pragma unroll
            for (int q = 0; q < 4; ++q) acc[i][j][q] = 0.f;

    uint4 ra[4], rb[4];

    auto ldA = [&](int kt) {
        const int k0 = kt << 5;
#pragma unroll
        for (int p = 0; p < 4; ++p) {
            int i = tid + (p << 8);
            int r = i >> 3, u = i & 7;
            float4 v = *(const float4*)(Ag + (size_t)r * K + k0 + (u << 2));
            ra[p].x = f2tf32(v.x); ra[p].y = f2tf32(v.y);
            ra[p].z = f2tf32(v.z); ra[p].w = f2tf32(v.w);
        }
    };
    auto stA = [&](int s) {
        uint4* as = (uint4*)(sm4 + AOFF(s));
#pragma unroll
        for (int p = 0; p < 4; ++p) {
            int i = tid + (p << 8);
            int r = i >> 3, u = i & 7;
            as[r * 8 + (u ^ (r & 7))] = ra[p];
        }
    };
    auto ldB = [&](int kt) {
        const int k0 = kt << 5;
#pragma unroll
        for (int p = 0; p < 4; ++p) {
            int i = tid + (p << 8);
            int k = i >> 5, n4 = (i & 31) << 2;
            float4 v = *(const float4*)(Bg + (size_t)(k0 + k) * N + n4);
            rb[p].x = f2tf32(v.x); rb[p].y = f2tf32(v.y);
            rb[p].z = f2tf32(v.z); rb[p].w = f2tf32(v.w);
        }
    };
    auto stB = [&](int s) {
        uint4* bs = (uint4*)(sm4 + BOFF(s));
#pragma unroll
        for (int p = 0; p < 4; ++p) {
            int i = tid + (p << 8);
            int k = i >> 5, n4 = (i & 31) << 2;
            bs[k * 32 + ((n4 >> 2) ^ ((k & 3) << 1))] = rb[p];
        }
    };

    auto compute = [&](int s) {
        const uint32_t* as = sm4 + AOFF(s);
        const uint32_t* bs = sm4 + BOFF(s);
#pragma unroll
        for (int ks = 0; ks < 4; ++ks) {
            const int kb = ks << 3;
            const int kq = kb + (lane & 3);
            uint32_t af[2][4];
#pragma unroll
            for (int i = 0; i < 2; ++i) {
                int m = wm * 32 + i * 16 + (lane >> 2);
                int sw = (m & 7) << 2;
                af[i][0] = as[m * 32 + (kq ^ sw)];
                af[i][1] = as[(m + 8) * 32 + (kq ^ sw)];       // (m+8)&7 == m&7
                af[i][2] = as[m * 32 + ((kq + 4) ^ sw)];
                af[i][3] = as[(m + 8) * 32 + ((kq + 4) ^ sw)];
            }
            const int ksw = (kq & 3) << 3;
#pragma unroll
            for (int j = 0; j < 8; ++j) {
                int n = wn * 64 + j * 8 + (lane >> 2);
                uint32_t b0 = bs[kq * 128 + (n ^ ksw)];
                uint32_t b1 = bs[(kq + 4) * 128 + (n ^ ksw)];  // (kq+4)&3 == kq&3
                mma_tf32(acc[0][j], af[0], b0, b1);
                mma_tf32(acc[1][j], af[1], b0, b1);
            }
        }
    };

    // ---- pipelined mainloop ----
    ldA(0); ldB(0);
    stA(0); stB(0);
    __syncthreads();
    for (int kt = 0; kt < NIT; ++kt) {
        const int cur = kt & 1;
        if (kt + 1 < NIT) { ldA(kt + 1); ldB(kt + 1); }
        compute(cur);
        if (kt + 1 < NIT) {
            stA(cur ^ 1); stB(cur ^ 1);
            __syncthreads();
        }
    }

    // ---- epilogue: accum regs + bias -> gmem (st.64) ----
#pragma unroll
    for (int i = 0; i < 2; ++i) {
        const int r = m0 + wm * 32 + i * 16 + (lane >> 2);
#pragma unroll
        for (int j = 0; j < 8; ++j) {
            const int c = n0 + wn * 64 + j * 8 + ((lane & 3) << 1);
            float2 bi = *(const float2*)&bias[c];
            float2 v0 = make_float2(acc[i][j][0] + bi.x, acc[i][j][1] + bi.y);
            float2 v1 = make_float2(acc[i][j][2] + bi.x, acc[i][j][3] + bi.y);
            *(float2*)&Cc[(size_t)r * N + c]       = v0;
            *(float2*)&Cc[(size_t)(r + 8) * N + c] = v1;
        }
    }
}

// ---------------------------------------------------------------------------
// Flash attention (causal), fp32 — unchanged (R1-proven).
// ---------------------------------------------------------------------------
#define QPAD 132
#define KPAD 65
#define VPAD 132
#define PPAD 68
#define KV_ELEMS (64*VPAD)
#define ATTN_SMEM ((64*QPAD + KV_ELEMS + 64*PPAD) * 4)

__global__ __launch_bounds__(256, 2) void attn_kernel()
{
    extern __shared__ __align__(16) float smf[];
    float* Qs  = smf;
    float* KVs = Qs + 64*QPAD;
    float* Ps  = KVs + KV_ELEMS;

    const int tid = threadIdx.x;
    const int tx = tid & 15, ty = tid >> 4;
    const int qt = blockIdx.x;
    const int b  = blockIdx.y >> 4, h = blockIdx.y & 15;
    const int q0 = qt * 64;
    const float* base = g_qkv + (size_t)b * T_ * C3_ + h * D_;

    for (int i = tid; i < 64*32; i += 256) {
        int r = i >> 5, c = (i & 31) << 2;
        *(float4*)&Qs[r*QPAD + c] =
            *(const float4*)(base + (size_t)(q0 + r) * C3_ + c);
    }

    float m_i[4], l_i[4], O[4][8];
#pragma unroll
    for (int i = 0; i < 4; i++) {
        m_i[i] = -3.0e38f; l_i[i] = 0.f;
#pragma unroll
        for (int j = 0; j < 8; j++) O[i][j] = 0.f;
    }

    const float scale = 0.08838834764831845f;

    for (int t = 0; t <= qt; ++t) {
        const int k0 = t * 64;
        __syncthreads();

        for (int i = tid; i < 64*128; i += 256) {
            int r = i >> 7, c = i & 127;
            KVs[c*KPAD + r] = base[C_ + (size_t)(k0 + r)*C3_ + c];
        }
        __syncthreads();

        float s[4][4];
#pragma unroll
        for (int i = 0; i < 4; i++)
#pragma unroll
            for (int j = 0; j < 4; j++) s[i][j] = 0.f;

#pragma unroll 4
        for (int kk = 0; kk < 128; ++kk) {
            float q[4], k[4];
#pragma unroll
            for (int i = 0; i < 4; i++) q[i] = Qs[(ty*4+i)*QPAD + kk];
#pragma unroll
            for (int j = 0; j < 4; j++) k[j] = KVs[kk*KPAD + tx + 16*j];
#pragma unroll
            for (int i = 0; i < 4; i++)
#pragma unroll
                for (int j = 0; j < 4; j++)
                    s[i][j] = fmaf(q[i], k[j], s[i][j]);
        }

#pragma unroll
        for (int i = 0; i < 4; i++) {
            const int gq = q0 + ty*4 + i;
            float sv[4];
            float mt = -3.0e38f;
#pragma unroll
            for (int j = 0; j < 4; j++) {
                int gk = k0 + tx + 16*j;
                float v = s[i][j] * scale;
                if (gk > gq) v = -1.0e9f;
                sv[j] = v;
                mt = fmaxf(mt, v);
            }
#pragma unroll
            for (int o = 8; o >= 1; o >>= 1)
                mt = fmaxf(mt, __shfl_xor_sync(0xffffffffu, mt, o, 16));
            const float mn = fmaxf(m_i[i], mt);
            float sum = 0.f;
#pragma unroll
            for (int j = 0; j < 4; j++) {
                float p = __expf(sv[j] - mn);
                sum += p;
                Ps[(ty*4+i)*PPAD + tx + 16*j] = p;
            }
#pragma unroll
            for (int o = 8; o >= 1; o >>= 1)
                sum += __shfl_xor_sync(0xffffffffu, sum, o, 16);
            const float corr = __expf(m_i[i] - mn);
            l_i[i] = l_i[i] * corr + sum;
            m_i[i] = mn;
#pragma unroll
            for (int j = 0; j < 8; j++) O[i][j] *= corr;
        }
        __syncthreads();

        for (int i = tid; i < 64*32; i += 256) {
            int r = i >> 5, c = (i & 31) << 2;
            *(float4*)&KVs[r*VPAD + c] =
                *(const float4*)(base + 2*C_ + (size_t)(k0 + r)*C3_ + c);
        }
        __syncthreads();

        for (int k4 = 0; k4 < 16; ++k4) {
            float p[4][4];
#pragma unroll
            for (int i = 0; i < 4; i++) {
                float4 p4 = *(const float4*)&Ps[(ty*4+i)*PPAD + k4*4];
                p[i][0]=p4.x; p[i][1]=p4.y; p[i][2]=p4.z; p[i][3]=p4.w;
            }
#pragma unroll
            for (int ss = 0; ss < 4; ++ss) {
                int k = k4*4 + ss;
                float4 v0 = *(const float4*)&KVs[k*VPAD + tx*8];
                float4 v1 = *(const float4*)&KVs[k*VPAD + tx*8 + 4];
                float vr[8] = {v0.x,v0.y,v0.z,v0.w,v1.x,v1.y,v1.z,v1.w};
#pragma unroll
                for (int i = 0; i < 4; i++)
#pragma unroll
                    for (int j = 0; j < 8; j++)
                        O[i][j] = fmaf(p[i][ss], vr[j], O[i][j]);
            }
        }
    }

#pragma unroll
    for (int i = 0; i < 4; i++) {
        const float inv = 1.0f / l_i[i];
        const size_t row = (size_t)b * T_ + q0 + ty*4 + i;
        float4 o0 = make_float4(O[i][0]*inv, O[i][1]*inv, O[i][2]*inv, O[i][3]*inv);
        float4 o1 = make_float4(O[i][4]*inv, O[i][5]*inv, O[i][6]*inv, O[i][7]*inv);
        *(float4*)&g_y[row*C_ + h*D_ + tx*8]     = o0;
        *(float4*)&g_y[row*C_ + h*D_ + tx*8 + 4] = o1;
    }
}

// ---------------------------------------------------------------------------
extern "C" void kernel_launch(void* const* d_in, const int* in_sizes, int n_in,
                              void* d_out, int out_size)
{
    const float* x      = (const float*)d_in[0];
    const float* W_attn = (const float*)d_in[1];
    const float* b_attn = (const float*)d_in[2];
    const float* W_proj = (const float*)d_in[3];
    const float* b_proj = (const float*)d_in[4];
    float* out = (float*)d_out;

    float* qkv_ptr = nullptr;
    float* y_ptr   = nullptr;
    cudaGetSymbolAddress((void**)&qkv_ptr, g_qkv);
    cudaGetSymbolAddress((void**)&y_ptr,   g_y);

    cudaFuncSetAttribute(gemm_mma,
                         cudaFuncAttributeMaxDynamicSharedMemorySize, GEMM_SMEM_B);
    cudaFuncSetAttribute(attn_kernel,
                         cudaFuncAttributeMaxDynamicSharedMemorySize, ATTN_SMEM);

    // 1) qkv = x @ W_attn + b_attn          [8192, 6144]
    gemm_mma<<<dim3(C3_/128, (B_*T_)/128), 256, GEMM_SMEM_B>>>(
        x, W_attn, b_attn, qkv_ptr, B_*T_, C3_, C_);

    // 2) causal flash attention -> g_y      [8192, 2048]
    attn_kernel<<<dim3(T_/64, B_*H_), 256, ATTN_SMEM>>>();

    // 3) out = y @ W_proj + b_proj          [8192, 2048]
    gemm_mma<<<dim3(C_/128, (B_*T_)/128), 256, GEMM_SMEM_B>>>(
        y_ptr, W_proj, b_proj, out, B_*T_, C_, C_);
}

// round 7
// speedup vs baseline: 2.8494x; 1.3726x over previous
#include <cuda_runtime.h>
#include <math.h>
#include <stdint.h>

#define B_ 8
#define T_ 1024
#define C_ 2048
#define H_ 16
#define D_ 128
#define C3_ (3*C_)

// Scratch (device globals: allocation-free kernel_launch).
__device__ float    g_qkv[(size_t)B_*T_*C3_];   // [B*T, 3C] fp32
__device__ float    g_y  [(size_t)B_*T_*C_];    // [B*T, C]  fp32
__device__ uint32_t g_xt [(size_t)B_*T_*C_];    // x  as tf32 bits
__device__ uint32_t g_wat[(size_t)C_*C3_];      // W_attn as tf32 bits
__device__ uint32_t g_wpt[(size_t)C_*C_];       // W_proj as tf32 bits
__device__ uint32_t g_yt [(size_t)B_*T_*C_];    // y  as tf32 bits

// ===========================================================================
// helpers (base PTX only — ptxas here targets plain sm_103; no tcgen05)
// ===========================================================================
__device__ __forceinline__ uint32_t f2tf32(float f) {
    uint32_t r;
    asm("cvt.rna.tf32.f32 %0, %1;" : "=r"(r) : "f"(f));
    return r;
}
__device__ __forceinline__ uint32_t smem_u32(const void* p) {
    uint32_t a;
    asm("{ .reg .u64 t; cvta.to.shared.u64 t, %1; cvt.u32.u64 %0, t; }"
        : "=r"(a) : "l"(p));
    return a;
}
__device__ __forceinline__ void mma_tf32(float* d, const uint32_t* a,
                                         uint32_t b0, uint32_t b1) {
    asm volatile(
        "mma.sync.aligned.m16n8k8.row.col.f32.tf32.tf32.f32 "
        "{%0,%1,%2,%3}, {%4,%5,%6,%7}, {%8,%9}, {%0,%1,%2,%3};"
        : "+f"(d[0]), "+f"(d[1]), "+f"(d[2]), "+f"(d[3])
        : "r"(a[0]), "r"(a[1]), "r"(a[2]), "r"(a[3]), "r"(b0), "r"(b1));
}
__device__ __forceinline__ void cp16(uint32_t dst, const void* src) {
    asm volatile("cp.async.cg.shared.global [%0], [%1], 16;"
                 :: "r"(dst), "l"(src));
}
__device__ __forceinline__ void cp_commit() {
    asm volatile("cp.async.commit_group;" ::: "memory");
}
template <int N>
__device__ __forceinline__ void cp_wait() {
    asm volatile("cp.async.wait_group %0;" :: "n"(N) : "memory");
}

// ===========================================================================
// elementwise fp32 -> tf32-bits (RNA) conversion
// ===========================================================================
__global__ void cvt_tf32_k(const float4* __restrict__ in,
                           uint4* __restrict__ out, int n4)
{
    int i = blockIdx.x * blockDim.x + threadIdx.x;
    if (i < n4) {
        float4 v = in[i];
        out[i] = make_uint4(f2tf32(v.x), f2tf32(v.y), f2tf32(v.z), f2tf32(v.w));
    }
}

// ===========================================================================
// tf32 tensor-core GEMM with 3-stage cp.async pipeline.
// C[M,N] = A[M,K] @ B[K,N] + bias[N];  A,B are PRE-CONVERTED tf32 bits.
// CTA 128x128, BK=32, 256 threads (8 warps 4x2), warp tile 32x64.
// Smem layouts + fragment paths identical to the R3-proven kernel:
//   A stage: uint4 unit (r,u) at r*8 + (u ^ (r&7))
//   B stage: uint4 unit (k,n4) at k*32 + ((n4>>2) ^ ((k&3)<<1))
// 3 stages x (16KB A + 16KB B) = 96KB dynamic smem; 2 CTAs/SM.
// ===========================================================================
#define GEMM_SMEM_CP 98304

__global__ __launch_bounds__(256, 2) void gemm_cp(
    const uint32_t* __restrict__ A, const uint32_t* __restrict__ Bm,
    const float* __restrict__ bias, float* __restrict__ Cc,
    int M, int N, int K)
{
    extern __shared__ __align__(16) uint32_t sm4[];
    const uint32_t smem_base = smem_u32(sm4);
    const int tid  = threadIdx.x;
    const int lane = tid & 31;
    const int warp = tid >> 5;
    const int wm = warp & 3, wn = warp >> 2;
    const int m0 = blockIdx.y * 128, n0 = blockIdx.x * 128;
    const int NIT = K >> 5;

    float acc[2][8][4];
#pragma unroll
    for (int i = 0; i < 2; ++i)
#pragma unroll
        for (int j = 0; j < 8; ++j)
#pragma unroll
            for (int q = 0; q < 4; ++q) acc[i][j][q] = 0.f;

    auto issue = [&](int kt, int s) {
        const int k0 = kt << 5;
        const uint32_t ab = smem_base + (uint32_t)(s * 4096) * 4;
#pragma unroll
        for (int p = 0; p < 4; ++p) {
            int i = tid + (p << 8);
            int r = i >> 3, u = i & 7;
            cp16(ab + (uint32_t)(r * 8 + (u ^ (r & 7))) * 16,
                 A + (size_t)(m0 + r) * K + k0 + (u << 2));
        }
        const uint32_t bb = smem_base + (uint32_t)(12288 + s * 4096) * 4;
#pragma unroll
        for (int p = 0; p < 4; ++p) {
            int i = tid + (p << 8);
            int k = i >> 5, n4 = (i & 31) << 2;
            cp16(bb + (uint32_t)(k * 32 + ((n4 >> 2) ^ ((k & 3) << 1))) * 16,
                 Bm + (size_t)(k0 + k) * N + n0 + n4);
        }
    };

    auto compute = [&](int s) {
        const uint32_t* as = sm4 + s * 4096;
        const uint32_t* bs = sm4 + 12288 + s * 4096;
#pragma unroll
        for (int ks = 0; ks < 4; ++ks) {
            const int kq = (ks << 3) + (lane & 3);
            uint32_t af[2][4];
#pragma unroll
            for (int i = 0; i < 2; ++i) {
                int m = wm * 32 + i * 16 + (lane >> 2);
                int sw = (m & 7) << 2;
                af[i][0] = as[m * 32 + (kq ^ sw)];
                af[i][1] = as[(m + 8) * 32 + (kq ^ sw)];
                af[i][2] = as[m * 32 + ((kq + 4) ^ sw)];
                af[i][3] = as[(m + 8) * 32 + ((kq + 4) ^ sw)];
            }
            const int ksw = (kq & 3) << 3;
#pragma unroll
            for (int j = 0; j < 8; ++j) {
                int n = wn * 64 + j * 8 + (lane >> 2);
                uint32_t b0 = bs[kq * 128 + (n ^ ksw)];
                uint32_t b1 = bs[(kq + 4) * 128 + (n ^ ksw)];
                mma_tf32(acc[0][j], af[0], b0, b1);
                mma_tf32(acc[1][j], af[1], b0, b1);
            }
        }
    };

    // ---- 3-stage pipeline: groups 0,1 = stages 0,1; iter kt commits kt+2 ----
    issue(0, 0); cp_commit();
    issue(1, 1); cp_commit();
    for (int kt = 0; kt < NIT; ++kt) {
        cp_wait<1>();            // group kt complete (<=1 younger pending)
        __syncthreads();         // its smem visible to all threads
        compute(kt % 3);
        if (kt + 2 < NIT) issue(kt + 2, (kt + 2) % 3);
        cp_commit();             // always commit (possibly empty) to keep count
    }

    // ---- epilogue: accum regs + bias -> gmem (R3-proven) ----
#pragma unroll
    for (int i = 0; i < 2; ++i) {
        const int r = m0 + wm * 32 + i * 16 + (lane >> 2);
#pragma unroll
        for (int j = 0; j < 8; ++j) {
            const int c = n0 + wn * 64 + j * 8 + ((lane & 3) << 1);
            float2 bi = *(const float2*)&bias[c];
            float2 v0 = make_float2(acc[i][j][0] + bi.x, acc[i][j][1] + bi.y);
            float2 v1 = make_float2(acc[i][j][2] + bi.x, acc[i][j][3] + bi.y);
            *(float2*)&Cc[(size_t)r * N + c]       = v0;
            *(float2*)&Cc[(size_t)(r + 8) * N + c] = v1;
        }
    }
}

// ---------------------------------------------------------------------------
// Flash attention (causal), fp32 — R1-proven kernel, VERBATIM.
// ---------------------------------------------------------------------------
#define QPAD 132
#define KPAD 65
#define VPAD 132
#define PPAD 68
#define KV_ELEMS (64*VPAD)
#define ATTN_SMEM ((64*QPAD + KV_ELEMS + 64*PPAD) * 4)

__global__ __launch_bounds__(256, 2) void attn_kernel()
{
    extern __shared__ __align__(16) float smf[];
    float* Qs  = smf;
    float* KVs = Qs + 64*QPAD;
    float* Ps  = KVs + KV_ELEMS;

    const int tid = threadIdx.x;
    const int tx = tid & 15, ty = tid >> 4;
    const int qt = blockIdx.x;
    const int b  = blockIdx.y >> 4, h = blockIdx.y & 15;
    const int q0 = qt * 64;
    const float* base = g_qkv + (size_t)b * T_ * C3_ + h * D_;

    for (int i = tid; i < 64*32; i += 256) {
        int r = i >> 5, c = (i & 31) << 2;
        *(float4*)&Qs[r*QPAD + c] =
            *(const float4*)(base + (size_t)(q0 + r) * C3_ + c);
    }

    float m_i[4], l_i[4], O[4][8];
#pragma unroll
    for (int i = 0; i < 4; i++) {
        m_i[i] = -3.0e38f; l_i[i] = 0.f;
#pragma unroll
        for (int j = 0; j < 8; j++) O[i][j] = 0.f;
    }

    const float scale = 0.08838834764831845f;

    for (int t = 0; t <= qt; ++t) {
        const int k0 = t * 64;
        __syncthreads();

        for (int i = tid; i < 64*128; i += 256) {
            int r = i >> 7, c = i & 127;
            KVs[c*KPAD + r] = base[C_ + (size_t)(k0 + r)*C3_ + c];
        }
        __syncthreads();

        float s[4][4];
#pragma unroll
        for (int i = 0; i < 4; i++)
#pragma unroll
            for (int j = 0; j < 4; j++) s[i][j] = 0.f;

#pragma unroll 4
        for (int kk = 0; kk < 128; ++kk) {
            float q[4], k[4];
#pragma unroll
            for (int i = 0; i < 4; i++) q[i] = Qs[(ty*4+i)*QPAD + kk];
#pragma unroll
            for (int j = 0; j < 4; j++) k[j] = KVs[kk*KPAD + tx + 16*j];
#pragma unroll
            for (int i = 0; i < 4; i++)
#pragma unroll
                for (int j = 0; j < 4; j++)
                    s[i][j] = fmaf(q[i], k[j], s[i][j]);
        }

#pragma unroll
        for (int i = 0; i < 4; i++) {
            const int gq = q0 + ty*4 + i;
            float sv[4];
            float mt = -3.0e38f;
#pragma unroll
            for (int j = 0; j < 4; j++) {
                int gk = k0 + tx + 16*j;
                float v = s[i][j] * scale;
                if (gk > gq) v = -1.0e9f;
                sv[j] = v;
                mt = fmaxf(mt, v);
            }
#pragma unroll
            for (int o = 8; o >= 1; o >>= 1)
                mt = fmaxf(mt, __shfl_xor_sync(0xffffffffu, mt, o, 16));
            const float mn = fmaxf(m_i[i], mt);
            float sum = 0.f;
#pragma unroll
            for (int j = 0; j < 4; j++) {
                float p = __expf(sv[j] - mn);
                sum += p;
                Ps[(ty*4+i)*PPAD + tx + 16*j] = p;
            }
#pragma unroll
            for (int o = 8; o >= 1; o >>= 1)
                sum += __shfl_xor_sync(0xffffffffu, sum, o, 16);
            const float corr = __expf(m_i[i] - mn);
            l_i[i] = l_i[i] * corr + sum;
            m_i[i] = mn;
#pragma unroll
            for (int j = 0; j < 8; j++) O[i][j] *= corr;
        }
        __syncthreads();

        for (int i = tid; i < 64*32; i += 256) {
            int r = i >> 5, c = (i & 31) << 2;
            *(float4*)&KVs[r*VPAD + c] =
                *(const float4*)(base + 2*C_ + (size_t)(k0 + r)*C3_ + c);
        }
        __syncthreads();

        for (int k4 = 0; k4 < 16; ++k4) {
            float p[4][4];
#pragma unroll
            for (int i = 0; i < 4; i++) {
                float4 p4 = *(const float4*)&Ps[(ty*4+i)*PPAD + k4*4];
                p[i][0]=p4.x; p[i][1]=p4.y; p[i][2]=p4.z; p[i][3]=p4.w;
            }
#pragma unroll
            for (int ss = 0; ss < 4; ++ss) {
                int k = k4*4 + ss;
                float4 v0 = *(const float4*)&KVs[k*VPAD + tx*8];
                float4 v1 = *(const float4*)&KVs[k*VPAD + tx*8 + 4];
                float vr[8] = {v0.x,v0.y,v0.z,v0.w,v1.x,v1.y,v1.z,v1.w};
#pragma unroll
                for (int i = 0; i < 4; i++)
#pragma unroll
                    for (int j = 0; j < 8; j++)
                        O[i][j] = fmaf(p[i][ss], vr[j], O[i][j]);
            }
        }
    }

#pragma unroll
    for (int i = 0; i < 4; i++) {
        const float inv = 1.0f / l_i[i];
        const size_t row = (size_t)b * T_ + q0 + ty*4 + i;
        float4 o0 = make_float4(O[i][0]*inv, O[i][1]*inv, O[i][2]*inv, O[i][3]*inv);
        float4 o1 = make_float4(O[i][4]*inv, O[i][5]*inv, O[i][6]*inv, O[i][7]*inv);
        *(float4*)&g_y[row*C_ + h*D_ + tx*8]     = o0;
        *(float4*)&g_y[row*C_ + h*D_ + tx*8 + 4] = o1;
    }
}

// ---------------------------------------------------------------------------
extern "C" void kernel_launch(void* const* d_in, const int* in_sizes, int n_in,
                              void* d_out, int out_size)
{
    const float* x      = (const float*)d_in[0];
    const float* W_attn = (const float*)d_in[1];
    const float* b_attn = (const float*)d_in[2];
    const float* W_proj = (const float*)d_in[3];
    const float* b_proj = (const float*)d_in[4];
    float* out = (float*)d_out;

    float *qkv_ptr = nullptr, *y_ptr = nullptr;
    uint32_t *xt = nullptr, *wat = nullptr, *wpt = nullptr, *yt = nullptr;
    cudaGetSymbolAddress((void**)&qkv_ptr, g_qkv);
    cudaGetSymbolAddress((void**)&y_ptr,   g_y);
    cudaGetSymbolAddress((void**)&xt,  g_xt);
    cudaGetSymbolAddress((void**)&wat, g_wat);
    cudaGetSymbolAddress((void**)&wpt, g_wpt);
    cudaGetSymbolAddress((void**)&yt,  g_yt);

    cudaFuncSetAttribute(gemm_cp,
                         cudaFuncAttributeMaxDynamicSharedMemorySize, GEMM_SMEM_CP);
    cudaFuncSetAttribute(attn_kernel,
                         cudaFuncAttributeMaxDynamicSharedMemorySize, ATTN_SMEM);

    // 0) one-shot tf32 conversions of GEMM inputs
    int n4;
    n4 = (B_*T_*C_) / 4;
    cvt_tf32_k<<<(n4 + 255) / 256, 256>>>((const float4*)x, (uint4*)xt, n4);
    n4 = (C_*C3_) / 4;
    cvt_tf32_k<<<(n4 + 255) / 256, 256>>>((const float4*)W_attn, (uint4*)wat, n4);
    n4 = (C_*C_) / 4;
    cvt_tf32_k<<<(n4 + 255) / 256, 256>>>((const float4*)W_proj, (uint4*)wpt, n4);

    // 1) qkv = x @ W_attn + b_attn          [8192, 6144]
    gemm_cp<<<dim3(C3_/128, (B_*T_)/128), 256, GEMM_SMEM_CP>>>(
        xt, wat, b_attn, qkv_ptr, B_*T_, C3_, C_);

    // 2) causal flash attention -> g_y      [8192, 2048]
    attn_kernel<<<dim3(T_/64, B_*H_), 256, ATTN_SMEM>>>();

    // 2b) y -> tf32 bits
    n4 = (B_*T_*C_) / 4;
    cvt_tf32_k<<<(n4 + 255) / 256, 256>>>((const float4*)y_ptr, (uint4*)yt, n4);

    // 3) out = y @ W_proj + b_proj          [8192, 2048]
    gemm_cp<<<dim3(C_/128, (B_*T_)/128), 256, GEMM_SMEM_CP>>>(
        yt, wpt, b_proj, out, B_*T_, C_, C_);
}